// round 10
// baseline (speedup 1.0000x reference)
#include <cuda_runtime.h>

#define BB 16
#define NN 1024
#define DD 1024   // D2H
#define UU 512
#define TOK (BB * NN)

#define DGRP 4                      // d-groups of 256
#define UCH  32                     // u-chunks
#define UC   (UU / UCH)             // 16 u per chunk
#define PRO  (DGRP * UCH)           // 128 prologue blocks

#define PB_PER_BATCH 64             // producer blocks per batch (16 rows each)
#define CB_PER_BATCH 128            // consumer blocks per batch (8 rows each)
#define BLK_PER_BATCH (PB_PER_BATCH + CB_PER_BATCH)   // 192

// Scratch (no device allocation allowed; rewritten every launch).
__device__ float g_ph[UCH * DD];
__device__ float g_pm[UCH * DD];
__device__ float g_vh[DD];
__device__ float g_vm[DD];
__device__ float g_const;
__device__ float g_sH[TOK];
__device__ float g_sM[TOK];
__device__ int   g_done[BB];

// ---------------------------------------------------------------------------
// Stage 1: v partials (proven 128-block geometry).  Block 0 zeroes g_done.
// ---------------------------------------------------------------------------
__global__ void k_pre(const float* __restrict__ Wh,
                      const float* __restrict__ Wm,
                      const float* __restrict__ wout) {
    int t = threadIdx.x;
    if (blockIdx.x == 0 && t < BB) g_done[t] = 0;

    int d  = (blockIdx.x & (DGRP - 1)) * 256 + t;
    int uc = blockIdx.x >> 2;               // / DGRP, 0..31
    int u0 = uc * UC;
    float ah = 0.f, am = 0.f;
#pragma unroll
    for (int i = 0; i < UC; ++i) {
        float w = __ldg(&wout[u0 + i]);
        ah = fmaf(Wh[(size_t)(u0 + i) * DD + d], w, ah);
        am = fmaf(Wm[(size_t)(u0 + i) * DD + d], w, am);
    }
    g_ph[uc * DD + d] = ah;
    g_pm[uc * DD + d] = am;
}

// ---------------------------------------------------------------------------
// Stage 2: blocks 0..3 fold partials into v_h/v_m; block 4 computes g_const.
// ---------------------------------------------------------------------------
__global__ void k_finish(const float* __restrict__ bh,
                         const float* __restrict__ bm,
                         const float* __restrict__ wout,
                         const float* __restrict__ bout) {
    int t = threadIdx.x;
    if (blockIdx.x < 4) {
        int d = blockIdx.x * 256 + t;
        float ah = 0.f, am = 0.f;
#pragma unroll
        for (int c = 0; c < UCH; ++c) {
            ah += g_ph[c * DD + d];
            am += g_pm[c * DD + d];
        }
        g_vh[d] = ah;
        g_vm[d] = am;
    } else {
        __shared__ float red[8];
        float acc = (bh[t] + bm[t]) * wout[t]
                  + (bh[t + 256] + bm[t + 256]) * wout[t + 256];
#pragma unroll
        for (int o = 16; o > 0; o >>= 1)
            acc += __shfl_down_sync(0xffffffffu, acc, o);
        if ((t & 31) == 0) red[t >> 5] = acc;
        __syncthreads();
        if (t < 8) {
            acc = red[t];
#pragma unroll
            for (int o = 4; o > 0; o >>= 1)
                acc += __shfl_down_sync(0x000000ffu, acc, o);
            if (t == 0) g_const = acc + bout[0];
        }
    }
}

// ---------------------------------------------------------------------------
// Stage 3: INTERLEAVED producer/consumer pipeline.
// Bid layout per batch b (192 blocks): [64 producers][128 consumers].
// Steady state: batch b's reads (DRAM) overlap batch b-1's writes (L2).
// Deadlock-free: every consumer waits only on strictly-lower-bid producers.
// ---------------------------------------------------------------------------
__global__ void __launch_bounds__(256, 3)
k_main(const float* __restrict__ x, float* __restrict__ out) {
    int bid = blockIdx.x;
    int t   = threadIdx.x;
    int grp = bid / BLK_PER_BATCH;          // batch 0..15
    int loc = bid - grp * BLK_PER_BATCH;    // 0..191

    if (loc < PB_PER_BATCH) {
        // ---- producer: 2 rows per warp, 16 rows per block ----
        int warp = t >> 5;
        int lane = t & 31;
        int r0   = grp * NN + loc * 16 + warp * 2;   // rows r0, r0+1
        const float4* x0  = reinterpret_cast<const float4*>(x + (size_t)r0 * DD);
        const float4* x1  = x0 + (DD / 4);
        const float4* vh4 = reinterpret_cast<const float4*>(g_vh);
        const float4* vm4 = reinterpret_cast<const float4*>(g_vm);

        float4 xa[8], xb[8];
#pragma unroll
        for (int i = 0; i < 8; ++i) xa[i] = __ldcs(&x0[lane + 32 * i]);
#pragma unroll
        for (int i = 0; i < 8; ++i) xb[i] = __ldcs(&x1[lane + 32 * i]);

        float ah0 = 0.f, am0 = 0.f, ah1 = 0.f, am1 = 0.f;
#pragma unroll
        for (int i = 0; i < 8; ++i) {
            int idx = lane + 32 * i;
            float4 h = vh4[idx];
            float4 m = vm4[idx];
            ah0 = fmaf(xa[i].x, h.x, fmaf(xa[i].y, h.y, fmaf(xa[i].z, h.z, fmaf(xa[i].w, h.w, ah0))));
            am0 = fmaf(xa[i].x, m.x, fmaf(xa[i].y, m.y, fmaf(xa[i].z, m.z, fmaf(xa[i].w, m.w, am0))));
            ah1 = fmaf(xb[i].x, h.x, fmaf(xb[i].y, h.y, fmaf(xb[i].z, h.z, fmaf(xb[i].w, h.w, ah1))));
            am1 = fmaf(xb[i].x, m.x, fmaf(xb[i].y, m.y, fmaf(xb[i].z, m.z, fmaf(xb[i].w, m.w, am1))));
        }
#pragma unroll
        for (int o = 16; o > 0; o >>= 1) {
            ah0 += __shfl_xor_sync(0xffffffffu, ah0, o);
            am0 += __shfl_xor_sync(0xffffffffu, am0, o);
            ah1 += __shfl_xor_sync(0xffffffffu, ah1, o);
            am1 += __shfl_xor_sync(0xffffffffu, am1, o);
        }
        if (lane == 0) {
            g_sH[r0]     = ah0;
            g_sH[r0 + 1] = ah1;
            g_sM[r0]     = am0;
            g_sM[r0 + 1] = am1;
            __threadfence();                        // release
        }
        __syncthreads();
        if (t == 0) atomicAdd(&g_done[grp], 1);
    } else {
        // ---- consumer: write 8 output rows of this batch ----
        int cb = loc - PB_PER_BATCH;        // 0..127
        int i0 = grp * NN + cb * 8;         // global row base (b*NN + i)

        if (t == 0) {
            while (*(volatile int*)&g_done[grp] < PB_PER_BATCH)
                __nanosleep(128);
            __threadfence();                // acquire
        }
        __syncthreads();

        float4 m = reinterpret_cast<const float4*>(g_sM + (size_t)grp * NN)[t];
        float  c = g_const;
        float4 h0 = reinterpret_cast<const float4*>(g_sH + i0)[0];
        float4 h1 = reinterpret_cast<const float4*>(g_sH + i0)[1];
        float base[8] = {h0.x + c, h0.y + c, h0.z + c, h0.w + c,
                         h1.x + c, h1.y + c, h1.z + c, h1.w + c};
#pragma unroll
        for (int r = 0; r < 8; ++r) {
            __stcs(reinterpret_cast<float4*>(out + (size_t)(i0 + r) * NN) + t,
                   make_float4(base[r] + m.x, base[r] + m.y,
                               base[r] + m.z, base[r] + m.w));
        }
    }
}

extern "C" void kernel_launch(void* const* d_in, const int* in_sizes, int n_in,
                              void* d_out, int out_size) {
    const float* x    = (const float*)d_in[0];
    const float* Wh   = (const float*)d_in[1];
    const float* bh   = (const float*)d_in[2];
    const float* Wm   = (const float*)d_in[3];
    const float* bm   = (const float*)d_in[4];
    const float* wout = (const float*)d_in[5];
    const float* bout = (const float*)d_in[6];
    float* out = (float*)d_out;

    k_pre<<<PRO, 256>>>(Wh, Wm, wout);
    k_finish<<<5, 256>>>(bh, bm, wout, bout);
    k_main<<<BB * BLK_PER_BATCH, 256>>>(x, out);
}

// round 11
// speedup vs baseline: 1.1372x; 1.1372x over previous
#include <cuda_runtime.h>

#define BB 16
#define NN 1024
#define DD 1024   // D2H
#define UU 512
#define TOK (BB * NN)

#define DGRP 4                      // d-groups of 256
#define UCH  32                     // u-chunks
#define UC   (UU / UCH)             // 16 u per chunk
#define PRO  (DGRP * UCH)           // 128 prologue blocks

#define ROW_BLOCKS (TOK / 16)       // 1024 (16 rows per block, warp per 2 rows)
#define OUT_BLOCKS (TOK / 8)        // 2048
#define RB_PER_BATCH (NN / 16)      // 64 row-blocks per batch

// Scratch (no device allocation allowed; rewritten every launch).
__device__ float g_ph[UCH * DD];
__device__ float g_pm[UCH * DD];
__device__ float g_vh[DD];
__device__ float g_vm[DD];
__device__ float g_const;
__device__ float g_sH[TOK];
__device__ float g_sM[TOK];
__device__ int   g_done[BB];
__device__ int   g_tick = 0;        // self-resetting ticket (last block zeroes it)

// ---------------------------------------------------------------------------
// Stage 1: v partials (proven 128-block geometry) + LAST-BLOCK fold.
// The last block to finish (atomic ticket) folds the 32 partials into
// v_h/v_m and computes g_const — removes the k_finish launch entirely.
// Reduction order is a fixed index loop -> deterministic output.
// Block 0 zeroes the g_done counters for this replay.
// ---------------------------------------------------------------------------
__global__ void k_pre(const float* __restrict__ Wh,
                      const float* __restrict__ Wm,
                      const float* __restrict__ wout,
                      const float* __restrict__ bh,
                      const float* __restrict__ bm,
                      const float* __restrict__ bout) {
    int t = threadIdx.x;
    if (blockIdx.x == 0 && t < BB) g_done[t] = 0;

    int d  = (blockIdx.x & (DGRP - 1)) * 256 + t;
    int uc = blockIdx.x >> 2;               // / DGRP, 0..31
    int u0 = uc * UC;
    float ah = 0.f, am = 0.f;
#pragma unroll
    for (int i = 0; i < UC; ++i) {
        float w = __ldg(&wout[u0 + i]);
        ah = fmaf(Wh[(size_t)(u0 + i) * DD + d], w, ah);
        am = fmaf(Wm[(size_t)(u0 + i) * DD + d], w, am);
    }
    g_ph[uc * DD + d] = ah;
    g_pm[uc * DD + d] = am;

    // ---- last-block fold ----
    __shared__ int s_last;
    __threadfence();
    __syncthreads();
    if (t == 0) s_last = (atomicAdd(&g_tick, 1) == PRO - 1);
    __syncthreads();
    if (!s_last) return;

    // fold 32 partials: each thread owns one float4 d-column
    const float4* ph4 = reinterpret_cast<const float4*>(g_ph);
    const float4* pm4 = reinterpret_cast<const float4*>(g_pm);
    float4 vh = make_float4(0.f, 0.f, 0.f, 0.f);
    float4 vm = make_float4(0.f, 0.f, 0.f, 0.f);
#pragma unroll
    for (int c = 0; c < UCH; ++c) {
        float4 a = ph4[c * (DD / 4) + t];
        float4 b = pm4[c * (DD / 4) + t];
        vh.x += a.x; vh.y += a.y; vh.z += a.z; vh.w += a.w;
        vm.x += b.x; vm.y += b.y; vm.z += b.z; vm.w += b.w;
    }
    reinterpret_cast<float4*>(g_vh)[t] = vh;
    reinterpret_cast<float4*>(g_vm)[t] = vm;

    // const: (b_h + b_m) . w_out + b_out  (256 threads x 2 u's)
    __shared__ float red[8];
    float acc = (bh[t] + bm[t]) * wout[t]
              + (bh[t + 256] + bm[t + 256]) * wout[t + 256];
#pragma unroll
    for (int o = 16; o > 0; o >>= 1)
        acc += __shfl_down_sync(0xffffffffu, acc, o);
    if ((t & 31) == 0) red[t >> 5] = acc;
    __syncthreads();
    if (t < 8) {
        acc = red[t];
#pragma unroll
        for (int o = 4; o > 0; o >>= 1)
            acc += __shfl_down_sync(0x000000ffu, acc, o);
        if (t == 0) {
            g_const = acc + bout[0];
            g_tick  = 0;            // reset ticket for the next replay
        }
    }
}

// ---------------------------------------------------------------------------
// Stage 2 (fused row+out pipeline, R4/R7 proven layout).
// Producer change: v_h/v_m staged in SMEM (8 KB) -> x is the ONLY LDG
// stream (1/3 of previous L1tex wavefronts); v read via conflict-free
// LDS.128 on the MIO pipe.
// ---------------------------------------------------------------------------
__global__ void __launch_bounds__(256, 3)
k_main(const float* __restrict__ x, float* __restrict__ out) {
    int bid = blockIdx.x;
    int t   = threadIdx.x;

    if (bid < ROW_BLOCKS) {
        // ---- producer: 2 rows per warp, 16 rows per block ----
        __shared__ float4 svh[DD / 4];
        __shared__ float4 svm[DD / 4];
        svh[t] = reinterpret_cast<const float4*>(g_vh)[t];
        svm[t] = reinterpret_cast<const float4*>(g_vm)[t];

        int warp = t >> 5;
        int lane = t & 31;
        int r0   = bid * 16 + warp * 2;     // rows r0, r0+1
        const float4* x0 = reinterpret_cast<const float4*>(x + (size_t)r0 * DD);
        const float4* x1 = x0 + (DD / 4);

        float4 xa[8], xb[8];
#pragma unroll
        for (int i = 0; i < 8; ++i) xa[i] = __ldcs(&x0[lane + 32 * i]);
#pragma unroll
        for (int i = 0; i < 8; ++i) xb[i] = __ldcs(&x1[lane + 32 * i]);

        __syncthreads();            // smem v ready

        float ah0 = 0.f, am0 = 0.f, ah1 = 0.f, am1 = 0.f;
#pragma unroll
        for (int i = 0; i < 8; ++i) {
            int idx = lane + 32 * i;
            float4 h = svh[idx];
            float4 m = svm[idx];
            ah0 = fmaf(xa[i].x, h.x, fmaf(xa[i].y, h.y, fmaf(xa[i].z, h.z, fmaf(xa[i].w, h.w, ah0))));
            am0 = fmaf(xa[i].x, m.x, fmaf(xa[i].y, m.y, fmaf(xa[i].z, m.z, fmaf(xa[i].w, m.w, am0))));
            ah1 = fmaf(xb[i].x, h.x, fmaf(xb[i].y, h.y, fmaf(xb[i].z, h.z, fmaf(xb[i].w, h.w, ah1))));
            am1 = fmaf(xb[i].x, m.x, fmaf(xb[i].y, m.y, fmaf(xb[i].z, m.z, fmaf(xb[i].w, m.w, am1))));
        }
#pragma unroll
        for (int o = 16; o > 0; o >>= 1) {
            ah0 += __shfl_xor_sync(0xffffffffu, ah0, o);
            am0 += __shfl_xor_sync(0xffffffffu, am0, o);
            ah1 += __shfl_xor_sync(0xffffffffu, ah1, o);
            am1 += __shfl_xor_sync(0xffffffffu, am1, o);
        }
        if (lane == 0) {
            g_sH[r0]     = ah0;
            g_sH[r0 + 1] = ah1;
            g_sM[r0]     = am0;
            g_sM[r0 + 1] = am1;
            __threadfence();                        // release
        }
        __syncthreads();
        if (t == 0) atomicAdd(&g_done[bid >> 6], 1);   // RB_PER_BATCH = 64
    } else {
        // ---- consumer: write 8 output rows of one batch ----
        int ob = bid - ROW_BLOCKS;
        int i0 = ob * 8;            // global row base (b*NN + i)
        int b  = i0 >> 10;          // NN = 1024

        if (t == 0) {
            while (*(volatile int*)&g_done[b] < RB_PER_BATCH)
                __nanosleep(128);
            __threadfence();        // acquire
        }
        __syncthreads();

        float4 m = reinterpret_cast<const float4*>(g_sM + (size_t)b * NN)[t];
        float  c = g_const;
        float4 h0 = reinterpret_cast<const float4*>(g_sH + i0)[0];
        float4 h1 = reinterpret_cast<const float4*>(g_sH + i0)[1];
        float base[8] = {h0.x + c, h0.y + c, h0.z + c, h0.w + c,
                         h1.x + c, h1.y + c, h1.z + c, h1.w + c};
#pragma unroll
        for (int r = 0; r < 8; ++r) {
            __stcs(reinterpret_cast<float4*>(out + (size_t)(i0 + r) * NN) + t,
                   make_float4(base[r] + m.x, base[r] + m.y,
                               base[r] + m.z, base[r] + m.w));
        }
    }
}

extern "C" void kernel_launch(void* const* d_in, const int* in_sizes, int n_in,
                              void* d_out, int out_size) {
    const float* x    = (const float*)d_in[0];
    const float* Wh   = (const float*)d_in[1];
    const float* bh   = (const float*)d_in[2];
    const float* Wm   = (const float*)d_in[3];
    const float* bm   = (const float*)d_in[4];
    const float* wout = (const float*)d_in[5];
    const float* bout = (const float*)d_in[6];
    float* out = (float*)d_out;

    k_pre<<<PRO, 256>>>(Wh, Wm, wout, bh, bm, bout);
    k_main<<<ROW_BLOCKS + OUT_BLOCKS, 256>>>(x, out);
}

// round 12
// speedup vs baseline: 1.2063x; 1.0608x over previous
#include <cuda_runtime.h>

#define BB 16
#define NN 1024
#define DD 1024   // D2H
#define UU 512
#define TOK (BB * NN)

#define DGRP 4                      // d-groups of 256
#define UCH  32                     // u-chunks
#define UC   (UU / UCH)             // 16 u per chunk
#define PRO  (DGRP * UCH)           // 128 prologue blocks

#define ROWS_PER_WARP 8
#define ROWS_PER_PBLK 64            // 8 warps x 8 rows
#define ROW_BLOCKS (TOK / ROWS_PER_PBLK)   // 256 producer blocks
#define OUT_BLOCKS (TOK / 8)        // 2048 consumer blocks
#define PB_PER_BATCH (NN / ROWS_PER_PBLK)  // 16 producer blocks per batch

// Scratch (no device allocation allowed; rewritten every launch).
__device__ float g_ph[UCH * DD];
__device__ float g_pm[UCH * DD];
__device__ float g_vh[DD];
__device__ float g_vm[DD];
__device__ float g_const;
__device__ float g_sH[TOK];
__device__ float g_sM[TOK];
__device__ int   g_done[BB];

// ---------------------------------------------------------------------------
// Stage 1: v partials (R7 proven: 128 blocks x 256 thr).  Block 0 zeroes
// the g_done counters for this replay.
// ---------------------------------------------------------------------------
__global__ void k_pre(const float* __restrict__ Wh,
                      const float* __restrict__ Wm,
                      const float* __restrict__ wout) {
    int t = threadIdx.x;
    if (blockIdx.x == 0 && t < BB) g_done[t] = 0;

    int d  = (blockIdx.x & (DGRP - 1)) * 256 + t;
    int uc = blockIdx.x >> 2;               // / DGRP, 0..31
    int u0 = uc * UC;
    float ah = 0.f, am = 0.f;
#pragma unroll
    for (int i = 0; i < UC; ++i) {
        float w = __ldg(&wout[u0 + i]);
        ah = fmaf(Wh[(size_t)(u0 + i) * DD + d], w, ah);
        am = fmaf(Wm[(size_t)(u0 + i) * DD + d], w, am);
    }
    g_ph[uc * DD + d] = ah;
    g_pm[uc * DD + d] = am;
}

// ---------------------------------------------------------------------------
// Stage 2: blocks 0..3 fold partials into v_h/v_m; block 4 computes g_const.
// ---------------------------------------------------------------------------
__global__ void k_finish(const float* __restrict__ bh,
                         const float* __restrict__ bm,
                         const float* __restrict__ wout,
                         const float* __restrict__ bout) {
    int t = threadIdx.x;
    if (blockIdx.x < 4) {
        int d = blockIdx.x * 256 + t;
        float ah = 0.f, am = 0.f;
#pragma unroll
        for (int c = 0; c < UCH; ++c) {
            ah += g_ph[c * DD + d];
            am += g_pm[c * DD + d];
        }
        g_vh[d] = ah;
        g_vm[d] = am;
    } else {
        __shared__ float red[8];
        float acc = (bh[t] + bm[t]) * wout[t]
                  + (bh[t + 256] + bm[t + 256]) * wout[t + 256];
#pragma unroll
        for (int o = 16; o > 0; o >>= 1)
            acc += __shfl_down_sync(0xffffffffu, acc, o);
        if ((t & 31) == 0) red[t >> 5] = acc;
        __syncthreads();
        if (t < 8) {
            acc = red[t];
#pragma unroll
            for (int o = 4; o > 0; o >>= 1)
                acc += __shfl_down_sync(0x000000ffu, acc, o);
            if (t == 0) g_const = acc + bout[0];
        }
    }
}

// ---------------------------------------------------------------------------
// Producer helpers: load a row slice / compute+publish one row.
// ---------------------------------------------------------------------------
__device__ __forceinline__ void load_row(float4 (&X)[8],
                                         const float4* xr, int lane) {
#pragma unroll
    for (int i = 0; i < 8; ++i) X[i] = __ldcs(&xr[lane + 32 * i]);
}

__device__ __forceinline__ void compute_row(const float4 (&X)[8],
                                            const float4* svh, const float4* svm,
                                            int lane, int row) {
    float ah = 0.f, am = 0.f;
#pragma unroll
    for (int i = 0; i < 8; ++i) {
        int idx = lane + 32 * i;
        float4 h = svh[idx];
        float4 m = svm[idx];
        ah = fmaf(X[i].x, h.x, fmaf(X[i].y, h.y, fmaf(X[i].z, h.z, fmaf(X[i].w, h.w, ah))));
        am = fmaf(X[i].x, m.x, fmaf(X[i].y, m.y, fmaf(X[i].z, m.z, fmaf(X[i].w, m.w, am))));
    }
#pragma unroll
    for (int o = 16; o > 0; o >>= 1) {
        ah += __shfl_xor_sync(0xffffffffu, ah, o);
        am += __shfl_xor_sync(0xffffffffu, am, o);
    }
    if (lane == 0) { g_sH[row] = ah; g_sM[row] = am; }
}

// ---------------------------------------------------------------------------
// Stage 3 (fused row+out pipeline).  Producer: warp owns 8 consecutive rows,
// double-buffered x registers -> loads for row r+1 in flight while row r
// computes; tail (fence/atomic) once per 64 rows.  256 producer blocks at
// 2 CTAs/SM = one wave.  Consumer: proven batch-gated 8-row writer.
// ---------------------------------------------------------------------------
__global__ void __launch_bounds__(256, 2)
k_main(const float* __restrict__ x, float* __restrict__ out) {
    int bid = blockIdx.x;
    int t   = threadIdx.x;

    if (bid < ROW_BLOCKS) {
        // ---- producer ----
        __shared__ float4 svh[DD / 4];
        __shared__ float4 svm[DD / 4];

        int warp = t >> 5;
        int lane = t & 31;
        int r0   = bid * ROWS_PER_PBLK + warp * ROWS_PER_WARP;
        const float4* xr = reinterpret_cast<const float4*>(x + (size_t)r0 * DD);

        float4 X[8], Y[8];
        load_row(X, xr, lane);                      // row 0 in flight first

        svh[t] = reinterpret_cast<const float4*>(g_vh)[t];
        svm[t] = reinterpret_cast<const float4*>(g_vm)[t];
        __syncthreads();

        const float4* vh = svh;
        const float4* vm = svm;
#pragma unroll
        for (int r = 0; r < ROWS_PER_WARP; r += 2) {
            if (r + 1 < ROWS_PER_WARP) load_row(Y, xr + (r + 1) * (DD / 4), lane);
            compute_row(X, vh, vm, lane, r0 + r);
            if (r + 2 < ROWS_PER_WARP) load_row(X, xr + (r + 2) * (DD / 4), lane);
            if (r + 1 < ROWS_PER_WARP) compute_row(Y, vh, vm, lane, r0 + r + 1);
        }

        __syncthreads();
        if (t == 0) {
            __threadfence();                        // one fence per block
            atomicAdd(&g_done[bid >> 4], 1);        // PB_PER_BATCH = 16
        }
    } else {
        // ---- consumer: write 8 output rows of one batch ----
        int ob = bid - ROW_BLOCKS;
        int i0 = ob * 8;            // global row base (b*NN + i)
        int b  = i0 >> 10;          // NN = 1024

        if (t == 0) {
            while (*(volatile int*)&g_done[b] < PB_PER_BATCH)
                __nanosleep(128);
            __threadfence();        // acquire
        }
        __syncthreads();

        float4 m = reinterpret_cast<const float4*>(g_sM + (size_t)b * NN)[t];
        float  c = g_const;
        float4 h0 = reinterpret_cast<const float4*>(g_sH + i0)[0];
        float4 h1 = reinterpret_cast<const float4*>(g_sH + i0)[1];
        float base[8] = {h0.x + c, h0.y + c, h0.z + c, h0.w + c,
                         h1.x + c, h1.y + c, h1.z + c, h1.w + c};
#pragma unroll
        for (int r = 0; r < 8; ++r) {
            __stcs(reinterpret_cast<float4*>(out + (size_t)(i0 + r) * NN) + t,
                   make_float4(base[r] + m.x, base[r] + m.y,
                               base[r] + m.z, base[r] + m.w));
        }
    }
}

extern "C" void kernel_launch(void* const* d_in, const int* in_sizes, int n_in,
                              void* d_out, int out_size) {
    const float* x    = (const float*)d_in[0];
    const float* Wh   = (const float*)d_in[1];
    const float* bh   = (const float*)d_in[2];
    const float* Wm   = (const float*)d_in[3];
    const float* bm   = (const float*)d_in[4];
    const float* wout = (const float*)d_in[5];
    const float* bout = (const float*)d_in[6];
    float* out = (float*)d_out;

    k_pre<<<PRO, 256>>>(Wh, Wm, wout);
    k_finish<<<5, 256>>>(bh, bm, wout, bout);
    k_main<<<ROW_BLOCKS + OUT_BLOCKS, 256>>>(x, out);
}

// round 13
// speedup vs baseline: 1.2306x; 1.0201x over previous
#include <cuda_runtime.h>

#define BB 16
#define NN 1024
#define DD 1024   // D2H
#define UU 512
#define TOK (BB * NN)

#define DGRP 4                      // d-groups of 256
#define UCH  64                     // u-chunks
#define UC   (UU / UCH)             // 8 u per chunk
#define PRO  (DGRP * UCH)           // 256 prologue blocks

#define ROW_BLOCKS (TOK / 16)       // 1024 (16 rows per block, warp per 2 rows)
#define OUT_BLOCKS (TOK / 32)       // 512 (32 rows per block)
#define RB_PER_BATCH (NN / 16)      // 64 producer blocks per batch

// Scratch (no device allocation allowed; rewritten every launch).
__device__ float g_ph[UCH * DD];
__device__ float g_pm[UCH * DD];
__device__ float g_vh[DD];
__device__ float g_vm[DD];
__device__ float g_const;
__device__ float g_sH[TOK];
__device__ float g_sM[TOK];
__device__ int   g_done[BB];

// ---------------------------------------------------------------------------
// Stage 1: v partials.  256 blocks x 256 threads, 8 u's each — covers all
// 148 SMs (the 128-block version left SMs idle and ran at 700 GB/s).
// Block 0 zeroes the g_done counters for this replay.
// ---------------------------------------------------------------------------
__global__ void k_pre(const float* __restrict__ Wh,
                      const float* __restrict__ Wm,
                      const float* __restrict__ wout) {
    int t = threadIdx.x;
    if (blockIdx.x == 0 && t < BB) g_done[t] = 0;

    int d  = (blockIdx.x & (DGRP - 1)) * 256 + t;
    int uc = blockIdx.x >> 2;               // / DGRP, 0..63
    int u0 = uc * UC;
    float ah = 0.f, am = 0.f;
#pragma unroll
    for (int i = 0; i < UC; ++i) {
        float w = __ldg(&wout[u0 + i]);
        ah = fmaf(Wh[(size_t)(u0 + i) * DD + d], w, ah);
        am = fmaf(Wm[(size_t)(u0 + i) * DD + d], w, am);
    }
    g_ph[uc * DD + d] = ah;
    g_pm[uc * DD + d] = am;
}

// ---------------------------------------------------------------------------
// Stage 2: blocks 0..3 fold the 64 partials into v_h/v_m (256 d each);
// block 4 computes g_const = (b_h + b_m) . w_out + b_out.
// ---------------------------------------------------------------------------
__global__ void k_finish(const float* __restrict__ bh,
                         const float* __restrict__ bm,
                         const float* __restrict__ wout,
                         const float* __restrict__ bout) {
    int t = threadIdx.x;
    if (blockIdx.x < 4) {
        int d = blockIdx.x * 256 + t;
        float ah = 0.f, am = 0.f;
#pragma unroll
        for (int c = 0; c < UCH; ++c) {
            ah += g_ph[c * DD + d];
            am += g_pm[c * DD + d];
        }
        g_vh[d] = ah;
        g_vm[d] = am;
    } else {
        __shared__ float red[8];
        float acc = (bh[t] + bm[t]) * wout[t]
                  + (bh[t + 256] + bm[t + 256]) * wout[t + 256];
#pragma unroll
        for (int o = 16; o > 0; o >>= 1)
            acc += __shfl_down_sync(0xffffffffu, acc, o);
        if ((t & 31) == 0) red[t >> 5] = acc;
        __syncthreads();
        if (t < 8) {
            acc = red[t];
#pragma unroll
            for (int o = 4; o > 0; o >>= 1)
                acc += __shfl_down_sync(0x000000ffu, acc, o);
            if (t == 0) g_const = acc + bout[0];
        }
    }
}

// ---------------------------------------------------------------------------
// Stage 3 (fused row+out pipeline, proven R7 producer).
// Producer: warp per 2 rows, 16 prefetched x-float4s, shared v loads.
// Consumer: 32 rows per block (4x fewer blocks than R7 -> less SM slot
// churn during the producer phase), batch-gated, __stcs.
// ---------------------------------------------------------------------------
__global__ void __launch_bounds__(256, 3)
k_main(const float* __restrict__ x, float* __restrict__ out) {
    int bid = blockIdx.x;
    int t   = threadIdx.x;

    if (bid < ROW_BLOCKS) {
        // ---- producer: 2 rows per warp ----
        int warp = t >> 5;
        int lane = t & 31;
        int r0   = bid * 16 + warp * 2;     // rows r0, r0+1
        const float4* x0  = reinterpret_cast<const float4*>(x + (size_t)r0 * DD);
        const float4* x1  = x0 + (DD / 4);
        const float4* vh4 = reinterpret_cast<const float4*>(g_vh);
        const float4* vm4 = reinterpret_cast<const float4*>(g_vm);

        float4 xa[8], xb[8];
#pragma unroll
        for (int i = 0; i < 8; ++i) xa[i] = __ldcs(&x0[lane + 32 * i]);
#pragma unroll
        for (int i = 0; i < 8; ++i) xb[i] = __ldcs(&x1[lane + 32 * i]);

        float ah0 = 0.f, am0 = 0.f, ah1 = 0.f, am1 = 0.f;
#pragma unroll
        for (int i = 0; i < 8; ++i) {
            int idx = lane + 32 * i;
            float4 h = vh4[idx];
            float4 m = vm4[idx];
            ah0 = fmaf(xa[i].x, h.x, fmaf(xa[i].y, h.y, fmaf(xa[i].z, h.z, fmaf(xa[i].w, h.w, ah0))));
            am0 = fmaf(xa[i].x, m.x, fmaf(xa[i].y, m.y, fmaf(xa[i].z, m.z, fmaf(xa[i].w, m.w, am0))));
            ah1 = fmaf(xb[i].x, h.x, fmaf(xb[i].y, h.y, fmaf(xb[i].z, h.z, fmaf(xb[i].w, h.w, ah1))));
            am1 = fmaf(xb[i].x, m.x, fmaf(xb[i].y, m.y, fmaf(xb[i].z, m.z, fmaf(xb[i].w, m.w, am1))));
        }
#pragma unroll
        for (int o = 16; o > 0; o >>= 1) {
            ah0 += __shfl_xor_sync(0xffffffffu, ah0, o);
            am0 += __shfl_xor_sync(0xffffffffu, am0, o);
            ah1 += __shfl_xor_sync(0xffffffffu, ah1, o);
            am1 += __shfl_xor_sync(0xffffffffu, am1, o);
        }
        if (lane == 0) {
            g_sH[r0]     = ah0;
            g_sH[r0 + 1] = ah1;
            g_sM[r0]     = am0;
            g_sM[r0 + 1] = am1;
            __threadfence();                        // release
        }
        __syncthreads();
        if (t == 0) atomicAdd(&g_done[bid >> 6], 1);   // RB_PER_BATCH = 64
    } else {
        // ---- consumer: write 32 output rows of one batch ----
        int ob = bid - ROW_BLOCKS;          // 0..511
        int i0 = ob * 32;                   // global row base (b*NN + i)
        int b  = i0 >> 10;                  // NN = 1024

        if (t == 0) {
            while (*(volatile int*)&g_done[b] < RB_PER_BATCH)
                __nanosleep(128);
            __threadfence();                // acquire
        }
        __syncthreads();

        float4 m = reinterpret_cast<const float4*>(g_sM + (size_t)b * NN)[t];
        float  c = g_const;

        float base[32];
#pragma unroll
        for (int q = 0; q < 8; ++q) {
            float4 h = reinterpret_cast<const float4*>(g_sH + i0)[q];
            base[q * 4 + 0] = h.x + c;
            base[q * 4 + 1] = h.y + c;
            base[q * 4 + 2] = h.z + c;
            base[q * 4 + 3] = h.w + c;
        }
#pragma unroll
        for (int r = 0; r < 32; ++r) {
            __stcs(reinterpret_cast<float4*>(out + (size_t)(i0 + r) * NN) + t,
                   make_float4(base[r] + m.x, base[r] + m.y,
                               base[r] + m.z, base[r] + m.w));
        }
    }
}

extern "C" void kernel_launch(void* const* d_in, const int* in_sizes, int n_in,
                              void* d_out, int out_size) {
    const float* x    = (const float*)d_in[0];
    const float* Wh   = (const float*)d_in[1];
    const float* bh   = (const float*)d_in[2];
    const float* Wm   = (const float*)d_in[3];
    const float* bm   = (const float*)d_in[4];
    const float* wout = (const float*)d_in[5];
    const float* bout = (const float*)d_in[6];
    float* out = (float*)d_out;

    k_pre<<<PRO, 256>>>(Wh, Wm, wout);
    k_finish<<<5, 256>>>(bh, bm, wout, bout);
    k_main<<<ROW_BLOCKS + OUT_BLOCKS, 256>>>(x, out);
}

// round 14
// speedup vs baseline: 1.2682x; 1.0306x over previous
#include <cuda_runtime.h>
#include <cstdint>

#define BB 16
#define NN 1024
#define DD 1024   // D2H
#define UU 512
#define TOK (BB * NN)

#define DGRP 4                      // d-groups of 256
#define UCH  64                     // u-chunks
#define UC   (UU / UCH)             // 8 u per chunk
#define PRO  (DGRP * UCH)           // 256 prologue blocks

#define ROWS_PER_WARP 8
#define ROW_BLOCKS (TOK / 64)       // 256 producer blocks (8 warps x 8 rows)
#define OUT_BLOCKS (TOK / 8)        // 2048 consumer blocks (8 rows each)
#define RB_PER_BATCH (NN / 8)       // 128 producer WARP-units per batch

// dynamic smem: v_h(256 f4) + v_m(256 f4) + 8 warps * 2 bufs * 256 f4
#define SMEM_F4   (512 + 8 * 512)
#define SMEM_BYTES (SMEM_F4 * 16)   // 73728

// Scratch (no device allocation allowed; rewritten every launch).
__device__ float g_ph[UCH * DD];
__device__ float g_pm[UCH * DD];
__device__ float g_vh[DD];
__device__ float g_vm[DD];
__device__ float g_const;
__device__ float g_sH[TOK];
__device__ float g_sM[TOK];
__device__ int   g_done[BB];

// ---------------------------------------------------------------------------
// Stage 1: v partials (256 blocks x 256 thr, proven).  Block 0 zeroes g_done.
// ---------------------------------------------------------------------------
__global__ void k_pre(const float* __restrict__ Wh,
                      const float* __restrict__ Wm,
                      const float* __restrict__ wout) {
    int t = threadIdx.x;
    if (blockIdx.x == 0 && t < BB) g_done[t] = 0;

    int d  = (blockIdx.x & (DGRP - 1)) * 256 + t;
    int uc = blockIdx.x >> 2;               // / DGRP, 0..63
    int u0 = uc * UC;
    float ah = 0.f, am = 0.f;
#pragma unroll
    for (int i = 0; i < UC; ++i) {
        float w = __ldg(&wout[u0 + i]);
        ah = fmaf(Wh[(size_t)(u0 + i) * DD + d], w, ah);
        am = fmaf(Wm[(size_t)(u0 + i) * DD + d], w, am);
    }
    g_ph[uc * DD + d] = ah;
    g_pm[uc * DD + d] = am;
}

// ---------------------------------------------------------------------------
// Stage 2: blocks 0..3 fold the 64 partials into v_h/v_m; block 4 -> g_const.
// ---------------------------------------------------------------------------
__global__ void k_finish(const float* __restrict__ bh,
                         const float* __restrict__ bm,
                         const float* __restrict__ wout,
                         const float* __restrict__ bout) {
    int t = threadIdx.x;
    if (blockIdx.x < 4) {
        int d = blockIdx.x * 256 + t;
        float ah = 0.f, am = 0.f;
#pragma unroll
        for (int c = 0; c < UCH; ++c) {
            ah += g_ph[c * DD + d];
            am += g_pm[c * DD + d];
        }
        g_vh[d] = ah;
        g_vm[d] = am;
    } else {
        __shared__ float red[8];
        float acc = (bh[t] + bm[t]) * wout[t]
                  + (bh[t + 256] + bm[t + 256]) * wout[t + 256];
#pragma unroll
        for (int o = 16; o > 0; o >>= 1)
            acc += __shfl_down_sync(0xffffffffu, acc, o);
        if ((t & 31) == 0) red[t >> 5] = acc;
        __syncthreads();
        if (t < 8) {
            acc = red[t];
#pragma unroll
            for (int o = 4; o > 0; o >>= 1)
                acc += __shfl_down_sync(0x000000ffu, acc, o);
            if (t == 0) g_const = acc + bout[0];
        }
    }
}

// ---------------------------------------------------------------------------
// cp.async helpers (per-warp pipeline; lane reads only its own chunks).
// ---------------------------------------------------------------------------
__device__ __forceinline__ void issue_row(uint32_t dst_s, const float* src, int lane) {
#pragma unroll
    for (int i = 0; i < 8; ++i)
        asm volatile("cp.async.cg.shared.global [%0], [%1], 16;"
                     :: "r"(dst_s + (uint32_t)((i * 32 + lane) * 16)),
                        "l"(src + (i * 32 + lane) * 4) : "memory");
    asm volatile("cp.async.commit_group;" ::: "memory");
}

__device__ __forceinline__ void compute_row(const float4* __restrict__ buf,
                                            const float4* __restrict__ svh,
                                            const float4* __restrict__ svm,
                                            int lane, int row) {
    float ah = 0.f, am = 0.f;
#pragma unroll
    for (int i = 0; i < 8; ++i) {
        int idx = i * 32 + lane;
        float4 xv = buf[idx];
        float4 h  = svh[idx];
        float4 m  = svm[idx];
        ah = fmaf(xv.x, h.x, fmaf(xv.y, h.y, fmaf(xv.z, h.z, fmaf(xv.w, h.w, ah))));
        am = fmaf(xv.x, m.x, fmaf(xv.y, m.y, fmaf(xv.z, m.z, fmaf(xv.w, m.w, am))));
    }
#pragma unroll
    for (int o = 16; o > 0; o >>= 1) {
        ah += __shfl_xor_sync(0xffffffffu, ah, o);
        am += __shfl_xor_sync(0xffffffffu, am, o);
    }
    if (lane == 0) { g_sH[row] = ah; g_sM[row] = am; }
}

// ---------------------------------------------------------------------------
// Stage 3 (fused row+out pipeline).
// Producer: cp.async smem-staged, per-warp double buffer -> loads stay in
// flight ~100% of warp lifetime with no register cost.  Per-warp fence+atomic.
// Consumer: proven R7 8-row batch-gated __stcs writer.
// ---------------------------------------------------------------------------
__global__ void __launch_bounds__(256, 3)
k_main(const float* __restrict__ x, float* __restrict__ out) {
    extern __shared__ float4 dyn[];
    int bid = blockIdx.x;
    int t   = threadIdx.x;

    if (bid < ROW_BLOCKS) {
        // ---- producer ----
        float4* svh  = dyn;                 // 256 f4
        float4* svm  = dyn + 256;           // 256 f4
        int warp = t >> 5;
        int lane = t & 31;
        float4* buf  = dyn + 512 + warp * 512;   // 2 x 256 f4
        uint32_t buf_s = (uint32_t)__cvta_generic_to_shared(buf);

        int r0 = bid * 64 + warp * ROWS_PER_WARP;
        const float* xb = x + (size_t)r0 * DD;

        issue_row(buf_s,            xb,      lane);   // row 0 -> slot 0
        issue_row(buf_s + 256 * 16, xb + DD, lane);   // row 1 -> slot 1

        svh[t] = reinterpret_cast<const float4*>(g_vh)[t];
        svm[t] = reinterpret_cast<const float4*>(g_vm)[t];
        __syncthreads();                    // v staged (loads already in flight)

#pragma unroll
        for (int r = 0; r < ROWS_PER_WARP; ++r) {
            if (r < ROWS_PER_WARP - 2)
                asm volatile("cp.async.wait_group 1;" ::: "memory");
            else
                asm volatile("cp.async.wait_group 0;" ::: "memory");
            compute_row(buf + (r & 1) * 256, svh, svm, lane, r0 + r);
            if (r + 2 < ROWS_PER_WARP)
                issue_row(buf_s + (r & 1) * 256 * 16, xb + (r + 2) * DD, lane);
        }

        if (lane == 0) {
            __threadfence();                            // release this warp's rows
            atomicAdd(&g_done[r0 >> 10], 1);            // RB_PER_BATCH = 128 warps
        }
    } else {
        // ---- consumer: write 8 output rows of one batch ----
        int ob = bid - ROW_BLOCKS;
        int i0 = ob * 8;            // global row base (b*NN + i)
        int b  = i0 >> 10;          // NN = 1024

        if (t == 0) {
            while (*(volatile int*)&g_done[b] < RB_PER_BATCH)
                __nanosleep(128);
            __threadfence();        // acquire
        }
        __syncthreads();

        float4 m = reinterpret_cast<const float4*>(g_sM + (size_t)b * NN)[t];
        float  c = g_const;
        float4 h0 = reinterpret_cast<const float4*>(g_sH + i0)[0];
        float4 h1 = reinterpret_cast<const float4*>(g_sH + i0)[1];
        float base[8] = {h0.x + c, h0.y + c, h0.z + c, h0.w + c,
                         h1.x + c, h1.y + c, h1.z + c, h1.w + c};
#pragma unroll
        for (int r = 0; r < 8; ++r) {
            __stcs(reinterpret_cast<float4*>(out + (size_t)(i0 + r) * NN) + t,
                   make_float4(base[r] + m.x, base[r] + m.y,
                               base[r] + m.z, base[r] + m.w));
        }
    }
}

extern "C" void kernel_launch(void* const* d_in, const int* in_sizes, int n_in,
                              void* d_out, int out_size) {
    const float* x    = (const float*)d_in[0];
    const float* Wh   = (const float*)d_in[1];
    const float* bh   = (const float*)d_in[2];
    const float* Wm   = (const float*)d_in[3];
    const float* bm   = (const float*)d_in[4];
    const float* wout = (const float*)d_in[5];
    const float* bout = (const float*)d_in[6];
    float* out = (float*)d_out;

    static bool attr_set = false;
    if (!attr_set) {   // idempotent config, not a stream op / allocation
        cudaFuncSetAttribute(k_main, cudaFuncAttributeMaxDynamicSharedMemorySize,
                             SMEM_BYTES);
        attr_set = true;
    }

    k_pre<<<PRO, 256>>>(Wh, Wm, wout);
    k_finish<<<5, 256>>>(bh, bm, wout, bout);
    k_main<<<ROW_BLOCKS + OUT_BLOCKS, 256, SMEM_BYTES>>>(x, out);
}